// round 5
// baseline (speedup 1.0000x reference)
#include <cuda_runtime.h>

// Problem constants
static constexpr int Tt = 4;
static constexpr int Bb = 16;
static constexpr int Cc = 512;
static constexpr int Nn = 1024;
static constexpr int Cr = 64;
static constexpr int TB = Tt * Bb;     // 64 rows
static constexpr int BC = Bb * Cc;     // 8192 channels

// Scratch (allocation-free: __device__ globals)
__device__ float g_buf[TB * Cc];       // GAP output [64, 512] row-major
__device__ float h1n_buf[TB * Cr];     // bn1 output [64, 64] row-major
// Monotonic grid-barrier state for the tail kernel (1 sync per launch,
// TAIL_NB arrivals per launch -> counter is a multiple of TAIL_NB at every
// launch start; barrier id B = ceil(v/TAIL_NB) is launch-count independent).
__device__ unsigned g_arrive;
__device__ volatile unsigned g_release;

static constexpr int TAIL_NB = 64;

// ---------------------------------------------------------------------------
// K1: LIF multistep (TAU=2, hard reset, v_th=1) + GAP over N.
// R2-proven shape: one block per TWO channels, 256 threads, 8 front-batched
// LDG.128 per thread, streaming loads.
// ---------------------------------------------------------------------------
__global__ void __launch_bounds__(256) lif_gap_kernel(const float* __restrict__ x) {
    const int bc0 = blockIdx.x * 2;
    const int bc1 = bc0 + 1;
    const int tid = threadIdx.x;

    const float4* __restrict__ xp = reinterpret_cast<const float4*>(x);

    float4 xa[Tt], xb[Tt];
    #pragma unroll
    for (int t = 0; t < Tt; t++) {
        xa[t] = __ldcs(&xp[(size_t)(t * BC + bc0) * 256 + tid]);
        xb[t] = __ldcs(&xp[(size_t)(t * BC + bc1) * 256 + tid]);
    }

    float va0=0.f, va1=0.f, va2=0.f, va3=0.f;
    float vb0=0.f, vb1=0.f, vb2=0.f, vb3=0.f;
    float c8[8];

    #pragma unroll
    for (int t = 0; t < Tt; t++) {
        float ca = 0.f, cb = 0.f;
        va0 = (va0 + xa[t].x) * 0.5f; { float s = (va0 >= 1.f) ? 1.f : 0.f; ca += s; va0 *= (1.f - s); }
        va1 = (va1 + xa[t].y) * 0.5f; { float s = (va1 >= 1.f) ? 1.f : 0.f; ca += s; va1 *= (1.f - s); }
        va2 = (va2 + xa[t].z) * 0.5f; { float s = (va2 >= 1.f) ? 1.f : 0.f; ca += s; va2 *= (1.f - s); }
        va3 = (va3 + xa[t].w) * 0.5f; { float s = (va3 >= 1.f) ? 1.f : 0.f; ca += s; va3 *= (1.f - s); }
        vb0 = (vb0 + xb[t].x) * 0.5f; { float s = (vb0 >= 1.f) ? 1.f : 0.f; cb += s; vb0 *= (1.f - s); }
        vb1 = (vb1 + xb[t].y) * 0.5f; { float s = (vb1 >= 1.f) ? 1.f : 0.f; cb += s; vb1 *= (1.f - s); }
        vb2 = (vb2 + xb[t].z) * 0.5f; { float s = (vb2 >= 1.f) ? 1.f : 0.f; cb += s; vb2 *= (1.f - s); }
        vb3 = (vb3 + xb[t].w) * 0.5f; { float s = (vb3 >= 1.f) ? 1.f : 0.f; cb += s; vb3 *= (1.f - s); }
        c8[t]     = ca;
        c8[t + 4] = cb;
    }

    __shared__ float sdata[8][8];   // [warp][val]
    const int lane = tid & 31;
    const int warp = tid >> 5;

    #pragma unroll
    for (int k = 0; k < 8; k++) {
        float val = c8[k];
        #pragma unroll
        for (int off = 16; off > 0; off >>= 1)
            val += __shfl_down_sync(0xffffffffu, val, off);
        if (lane == 0) sdata[warp][k] = val;
    }
    __syncthreads();

    if (tid < 8) {
        float s = 0.f;
        #pragma unroll
        for (int w = 0; w < 8; w++) s += sdata[w][tid];
        const int t  = tid & 3;
        const int bc = (tid < 4) ? bc0 : bc1;
        g_buf[t * BC + bc] = s * (1.0f / (float)Nn);
    }
}

// ---------------------------------------------------------------------------
// K2 (tail): mm1+bn1, grid sync, mm2+bn2+out. 64 blocks x 256 threads, all
// resident; perfectly balanced (64 | 64 and 64 | 512).
// ---------------------------------------------------------------------------
__global__ void __launch_bounds__(256) tail_kernel(
    const float* __restrict__ w1, const float* __restrict__ b1,
    const float* __restrict__ gamma1, const float* __restrict__ beta1,
    const float* __restrict__ w2, const float* __restrict__ b2,
    const float* __restrict__ gamma2, const float* __restrict__ beta2,
    float* __restrict__ out)
{
    __shared__ float sh[4240];
    const int tid  = threadIdx.x;
    const int lane = tid & 31;
    const int warp = tid >> 5;

    // ---- Phase B: mm1 + bn1, block j = output column j ----
    {
        float* ws    = sh;        // [512]
        float* h1s   = sh + 512;  // [64]
        float* stats = sh + 576;  // [2]
        const int j = blockIdx.x;

        for (int i = tid; i < Cc; i += 256) ws[i] = w1[(size_t)j * Cc + i];
        __syncthreads();

        const float b1j = b1[j];
        #pragma unroll
        for (int k = 0; k < 8; k++) {
            const int r = warp * 8 + k;
            const float* __restrict__ gr = g_buf + (size_t)r * Cc;
            float acc = 0.f;
            #pragma unroll
            for (int i = 0; i < 16; i++)
                acc += gr[i * 32 + lane] * ws[i * 32 + lane];
            #pragma unroll
            for (int off = 16; off > 0; off >>= 1)
                acc += __shfl_down_sync(0xffffffffu, acc, off);
            if (lane == 0) h1s[r] = acc + b1j;
        }
        __syncthreads();

        if (warp == 0) {
            float a = h1s[lane], b = h1s[lane + 32];
            float s  = a + b;
            float ss = a * a + b * b;
            #pragma unroll
            for (int off = 16; off > 0; off >>= 1) {
                s  += __shfl_down_sync(0xffffffffu, s,  off);
                ss += __shfl_down_sync(0xffffffffu, ss, off);
            }
            if (lane == 0) {
                float mu  = s * (1.0f / TB);
                float var = ss * (1.0f / TB) - mu * mu;
                if (var < 0.f) var = 0.f;
                stats[0] = mu;
                stats[1] = rsqrtf(var + 1e-5f) * gamma1[j];
            }
        }
        __syncthreads();

        if (tid < TB)
            h1n_buf[tid * Cr + j] = (h1s[tid] - stats[0]) * stats[1] + beta1[j];
    }

    // ---- grid-wide barrier (monotonic; 64 arrivals per launch) ----
    {
        __threadfence();
        __syncthreads();
        if (tid == 0) {
            unsigned v = atomicAdd(&g_arrive, 1u) + 1u;
            unsigned B = (v + (unsigned)TAIL_NB - 1u) / (unsigned)TAIL_NB;
            if (v == B * (unsigned)TAIL_NB) g_release = B;
            while (g_release < B) { __nanosleep(32); }
            __threadfence();
        }
        __syncthreads();
    }

    // ---- Phase C: mm2 + bn2 + out; block handles 8 columns c ----
    {
        float* h1s  = sh;          // [64 * 65] padded
        float* w2s  = sh + 4160;   // [64]
        float* wsum = sh + 4224;   // [4]

        const float4* __restrict__ hp = reinterpret_cast<const float4*>(h1n_buf);
        for (int i4 = tid; i4 < (TB * Cr) / 4; i4 += 256) {
            float4 v = hp[i4];
            const int i  = i4 * 4;
            const int rr = i >> 6, jj = i & 63;
            float* d = &h1s[rr * 65 + jj];
            d[0] = v.x; d[1] = v.y; d[2] = v.z; d[3] = v.w;
        }
        __syncthreads();

        for (int c = blockIdx.x; c < Cc; c += TAIL_NB) {
            if (tid < Cr) w2s[tid] = w2[(size_t)c * Cr + tid];
            __syncthreads();

            float h = 0.f;
            if (tid < TB) {
                const float* __restrict__ hr = h1s + tid * 65;
                float acc = 0.f;
                #pragma unroll
                for (int j = 0; j < Cr; j++) acc += hr[j] * w2s[j];
                h = acc + b2[c];

                float s = h, ss = h * h;
                #pragma unroll
                for (int off = 16; off > 0; off >>= 1) {
                    s  += __shfl_down_sync(0xffffffffu, s,  off);
                    ss += __shfl_down_sync(0xffffffffu, ss, off);
                }
                if (lane == 0) { wsum[warp * 2] = s; wsum[warp * 2 + 1] = ss; }
            }
            __syncthreads();

            if (tid < TB) {
                const float S  = wsum[0] + wsum[2];
                const float SS = wsum[1] + wsum[3];
                const float mu = S * (1.0f / TB);
                float var = SS * (1.0f / TB) - mu * mu;
                if (var < 0.f) var = 0.f;
                const float sc = rsqrtf(var + 1e-5f) * gamma2[c];
                out[tid * Cc + c] = (h - mu) * sc + beta2[c];
            }
            __syncthreads();
        }
    }
}

// ---------------------------------------------------------------------------
extern "C" void kernel_launch(void* const* d_in, const int* in_sizes, int n_in,
                              void* d_out, int out_size) {
    const float* x      = (const float*)d_in[0];
    const float* w1     = (const float*)d_in[1];
    const float* b1     = (const float*)d_in[2];
    const float* gamma1 = (const float*)d_in[3];
    const float* beta1  = (const float*)d_in[4];
    const float* w2     = (const float*)d_in[5];
    const float* b2     = (const float*)d_in[6];
    const float* gamma2 = (const float*)d_in[7];
    const float* beta2  = (const float*)d_in[8];
    float* out = (float*)d_out;

    lif_gap_kernel<<<BC / 2, 256>>>(x);
    tail_kernel<<<TAIL_NB, 256>>>(w1, b1, gamma1, beta1,
                                  w2, b2, gamma2, beta2, out);
}